// round 9
// baseline (speedup 1.0000x reference)
#include <cuda_runtime.h>
#include <math.h>

#define BB 8
#define MM 1024
#define EE 1536
#define DD 256
#define HH 8
#define LN_EPS 1e-5f
#define CAP 256

// ---------------- scratch ----------------
__device__ float g_qkv[BB*MM*3*DD];
__device__ float g_attn[BB*MM*DD];
__device__ float g_A[BB*MM*DD];
__device__ float g_S[BB*EE*DD];
__device__ float g_Ep[BB*EE*DD];
__device__ float g_Y1[BB*MM*DD];
__device__ float g_Y[BB*MM*DD];
__device__ float g_sum[BB*DD];          // column sums of exp(S), atomically accumulated
__device__ unsigned short g_csc_idx[(size_t)BB*EE*CAP];
__device__ int            g_csc_cnt[BB*EE];
__device__ unsigned short g_csr_idx[(size_t)BB*MM*CAP];
__device__ int            g_csr_cnt[BB*MM];

// ---------------- tf32 mma helpers ----------------
__device__ __forceinline__ unsigned tf32c(float f) {
    unsigned r;
    asm("cvt.rna.tf32.f32 %0, %1;" : "=r"(r) : "f"(f));
    return r;
}
__device__ __forceinline__ void mma_tf32(float4& d, unsigned a0, unsigned a1,
                                         unsigned a2, unsigned a3,
                                         unsigned b0, unsigned b1) {
    asm volatile(
        "mma.sync.aligned.m16n8k8.row.col.f32.tf32.tf32.f32 "
        "{%0,%1,%2,%3}, {%4,%5,%6,%7}, {%8,%9}, {%0,%1,%2,%3};"
        : "+f"(d.x), "+f"(d.y), "+f"(d.z), "+f"(d.w)
        : "r"(a0), "r"(a1), "r"(a2), "r"(a3), "r"(b0), "r"(b1));
}
__device__ __forceinline__ void cp16(const void* smem, const void* gmem) {
    unsigned sa = (unsigned)__cvta_generic_to_shared(smem);
    asm volatile("cp.async.cg.shared.global [%0], [%1], 16;" :: "r"(sa), "l"(gmem) : "memory");
}

// ---------------- dense GEMM body: C = A[M,K] @ W[N,K]^T (+bias) ----------------
// SOFTW: A-load computes  a = S * exp(S) / colsum[b][k]
template<bool BIAS, bool SOFTW>
__device__ __forceinline__ void
gemm_body(const float* __restrict__ A, const float* __restrict__ W,
          const float* __restrict__ bias, float* __restrict__ C,
          int Ndim, int Kdim, const float* __restrict__ sump,
          int bx, int by)
{
    const int m0 = by * 128;
    const int n0 = bx * 128;
    const int tid = threadIdx.x;
    const int warp = tid >> 5, lane = tid & 31;
    const int wr = warp >> 2, wc = warp & 3;
    const int g = lane >> 2, t = lane & 3;
    const int bb0 = m0 / EE;

    __shared__ unsigned As[128 * 36];
    __shared__ unsigned Bs[128 * 36];
    __shared__ float sinv[256];

    if (SOFTW) {
        sinv[tid] = 1.f / sump[bb0 * DD + tid];
        __syncthreads();
    }

    float4 acc[4][4];
#pragma unroll
    for (int i = 0; i < 4; i++)
#pragma unroll
        for (int j = 0; j < 4; j++) acc[i][j] = make_float4(0.f, 0.f, 0.f, 0.f);

    const int lr = tid >> 3;
    const int lc = (tid & 7) * 4;

    for (int kt = 0; kt < Kdim; kt += 32) {
#pragma unroll
        for (int p = 0; p < 4; p++) {
            int r = lr + p * 32;
            float4 va = *(const float4*)(A + (size_t)(m0 + r) * Kdim + kt + lc);
            if (SOFTW) {
                va.x = va.x * __expf(va.x) * sinv[kt + lc];
                va.y = va.y * __expf(va.y) * sinv[kt + lc + 1];
                va.z = va.z * __expf(va.z) * sinv[kt + lc + 2];
                va.w = va.w * __expf(va.w) * sinv[kt + lc + 3];
            }
            float4 vb = *(const float4*)(W + (size_t)(n0 + r) * Kdim + kt + lc);
            uint4 ua = make_uint4(tf32c(va.x), tf32c(va.y), tf32c(va.z), tf32c(va.w));
            uint4 ub = make_uint4(tf32c(vb.x), tf32c(vb.y), tf32c(vb.z), tf32c(vb.w));
            *(uint4*)&As[r * 36 + lc] = ua;
            *(uint4*)&Bs[r * 36 + lc] = ub;
        }
        __syncthreads();
#pragma unroll
        for (int ks = 0; ks < 4; ks++) {
            const int k0 = ks * 8;
            unsigned af[4][4];
#pragma unroll
            for (int ms = 0; ms < 4; ms++) {
                int row = wr * 64 + ms * 16 + g;
                af[ms][0] = As[row * 36 + k0 + t];
                af[ms][1] = As[(row + 8) * 36 + k0 + t];
                af[ms][2] = As[row * 36 + k0 + 4 + t];
                af[ms][3] = As[(row + 8) * 36 + k0 + 4 + t];
            }
            unsigned bf[4][2];
#pragma unroll
            for (int ns = 0; ns < 4; ns++) {
                int nrow = wc * 32 + ns * 8 + g;
                bf[ns][0] = Bs[nrow * 36 + k0 + t];
                bf[ns][1] = Bs[nrow * 36 + k0 + 4 + t];
            }
#pragma unroll
            for (int ms = 0; ms < 4; ms++)
#pragma unroll
                for (int ns = 0; ns < 4; ns++)
                    mma_tf32(acc[ms][ns], af[ms][0], af[ms][1], af[ms][2], af[ms][3],
                             bf[ns][0], bf[ns][1]);
        }
        __syncthreads();
    }

#pragma unroll
    for (int ms = 0; ms < 4; ms++) {
        int r0 = m0 + wr * 64 + ms * 16 + g;
#pragma unroll
        for (int ns = 0; ns < 4; ns++) {
            int col = n0 + wc * 32 + ns * 8 + t * 2;
            float bx2 = 0.f, by2 = 0.f;
            if (BIAS) { bx2 = bias[col]; by2 = bias[col + 1]; }
            float2 v0 = make_float2(acc[ms][ns].x + bx2, acc[ms][ns].y + by2);
            float2 v1 = make_float2(acc[ms][ns].z + bx2, acc[ms][ns].w + by2);
            *(float2*)(C + (size_t)r0 * Ndim + col)       = v0;
            *(float2*)(C + (size_t)(r0 + 8) * Ndim + col) = v1;
        }
    }
}

template<bool BIAS, bool SOFTW>
__global__ void __launch_bounds__(256)
gemm_mma(const float* __restrict__ A, const float* __restrict__ W,
         const float* __restrict__ bias, float* __restrict__ C,
         int Ndim, int Kdim, const float* __restrict__ sump)
{
    gemm_body<BIAS, SOFTW>(A, W, bias, C, Ndim, Kdim, sump, blockIdx.x, blockIdx.y);
}

// ---------------- stage1 fat kernel: QKV gemm + inc copy + g_sum zero ----------------
#define T1_GEMM 384
#define T1_COPY (T1_GEMM + 1024)
#define T1_TOT  (T1_COPY + 1)

__global__ void __launch_bounds__(256)
stage1(const float* __restrict__ feat, const float* __restrict__ Win,
       const float* __restrict__ bin, float* __restrict__ qkv,
       const float* __restrict__ inc, float* __restrict__ out_inc, int do_copy)
{
    const int bid = blockIdx.x;
    const int tid = threadIdx.x;
    if (bid < T1_GEMM) {
        gemm_body<true, false>(feat, Win, bin, qkv, 768, 256, nullptr, bid % 6, bid / 6);
    } else if (bid < T1_COPY) {
        if (do_copy) {
            const int n4 = BB * MM * EE / 4;
            const int stride = 1024 * 256;
            for (int i = (bid - T1_GEMM) * 256 + tid; i < n4; i += stride)
                ((float4*)out_inc)[i] = ((const float4*)inc)[i];
        }
    } else {
        for (int i = tid; i < BB * DD; i += 256) g_sum[i] = 0.f;
    }
}

// ---------------- attention body: cp.async double-buffered K/V, tf32 mma ----------------
// smem raw f32: K stride 36 (bank 4g+t ok), V stride 40 (bank 8t+g ok); 2 buffers.
#define KBUF (64 * 36)
#define VBUF (64 * 40)

__device__ __forceinline__ void
attn_body(const float* __restrict__ qkv, float* __restrict__ out,
          int bh, int qt, float* Ksf, float* Vsf)
{
    const int b = bh >> 3, h = bh & 7;
    const int tid = threadIdx.x;
    const int warp = tid >> 5, lane = tid & 31;
    const int g = lane >> 2, t = lane & 3;
    const int qw = qt * 256 + warp * 32;

    const int lr = tid >> 3;
    const int lc = (tid & 7) * 4;

    const float scale = 0.17677669529663687f;
    unsigned qf[2][4][4];
#pragma unroll
    for (int q2 = 0; q2 < 2; q2++) {
        const float* q0 = qkv + (size_t)(b * MM + qw + q2 * 16 + g) * 768 + h * 32;
        const float* q1 = qkv + (size_t)(b * MM + qw + q2 * 16 + g + 8) * 768 + h * 32;
#pragma unroll
        for (int ks = 0; ks < 4; ks++) {
            qf[q2][ks][0] = tf32c(q0[ks * 8 + t] * scale);
            qf[q2][ks][1] = tf32c(q1[ks * 8 + t] * scale);
            qf[q2][ks][2] = tf32c(q0[ks * 8 + 4 + t] * scale);
            qf[q2][ks][3] = tf32c(q1[ks * 8 + 4 + t] * scale);
        }
    }

    float4 o0[4], o1[4];
#pragma unroll
    for (int i = 0; i < 4; i++) {
        o0[i] = make_float4(0.f, 0.f, 0.f, 0.f);
        o1[i] = make_float4(0.f, 0.f, 0.f, 0.f);
    }
    float l00 = 0.f, l01 = 0.f, l10 = 0.f, l11 = 0.f;

    const unsigned fullm = 0xffffffffu;
    const int src0 = (lane & 28) | (t >> 1);
    const int src2 = src0 + 2;
    const bool odd = (t & 1);

    // stage chunk 0 into buffer 0
    {
#pragma unroll
        for (int p = 0; p < 2; p++) {
            int r = lr + p * 32;
            const float* src = qkv + (size_t)(b * MM + r) * 768 + h * 32 + lc;
            cp16(&Ksf[r * 36 + lc], src + 256);
            cp16(&Vsf[r * 40 + lc], src + 512);
        }
        asm volatile("cp.async.commit_group;" ::: "memory");
    }

    for (int ch = 0; ch < 16; ch++) {
        const int cur = ch & 1;
        if (ch < 15) {
            const int nbase = (ch + 1) * 64;
            const int nb = cur ^ 1;
#pragma unroll
            for (int p = 0; p < 2; p++) {
                int r = lr + p * 32;
                const float* src = qkv + (size_t)(b * MM + nbase + r) * 768 + h * 32 + lc;
                cp16(&Ksf[nb * KBUF + r * 36 + lc], src + 256);
                cp16(&Vsf[nb * VBUF + r * 40 + lc], src + 512);
            }
            asm volatile("cp.async.commit_group;" ::: "memory");
            asm volatile("cp.async.wait_group 1;" ::: "memory");
        } else {
            asm volatile("cp.async.wait_group 0;" ::: "memory");
        }
        __syncthreads();

        const float* Kc = Ksf + cur * KBUF;
        const float* Vc = Vsf + cur * VBUF;

#pragma unroll
        for (int ns = 0; ns < 8; ns++) {
            float4 s0 = make_float4(0.f, 0.f, 0.f, 0.f);
            float4 s1 = make_float4(0.f, 0.f, 0.f, 0.f);
#pragma unroll
            for (int ks = 0; ks < 4; ks++) {
                int nrow = ns * 8 + g;
                unsigned b0 = tf32c(Kc[nrow * 36 + ks * 8 + t]);
                unsigned b1 = tf32c(Kc[nrow * 36 + ks * 8 + 4 + t]);
                mma_tf32(s0, qf[0][ks][0], qf[0][ks][1], qf[0][ks][2], qf[0][ks][3], b0, b1);
                mma_tf32(s1, qf[1][ks][0], qf[1][ks][1], qf[1][ks][2], qf[1][ks][3], b0, b1);
            }
            s0.x = __expf(s0.x); s0.y = __expf(s0.y); s0.z = __expf(s0.z); s0.w = __expf(s0.w);
            s1.x = __expf(s1.x); s1.y = __expf(s1.y); s1.z = __expf(s1.z); s1.w = __expf(s1.w);
            l00 += s0.x + s0.y; l01 += s0.z + s0.w;
            l10 += s1.x + s1.y; l11 += s1.z + s1.w;

            float ax0 = __shfl_sync(fullm, s0.x, src0);
            float ay0 = __shfl_sync(fullm, s0.y, src0);
            float az0 = __shfl_sync(fullm, s0.z, src0);
            float aw0 = __shfl_sync(fullm, s0.w, src0);
            float ax2 = __shfl_sync(fullm, s0.x, src2);
            float ay2 = __shfl_sync(fullm, s0.y, src2);
            float az2 = __shfl_sync(fullm, s0.z, src2);
            float aw2 = __shfl_sync(fullm, s0.w, src2);
            unsigned pa0 = tf32c(odd ? ay0 : ax0);
            unsigned pa1 = tf32c(odd ? aw0 : az0);
            unsigned pa2 = tf32c(odd ? ay2 : ax2);
            unsigned pa3 = tf32c(odd ? aw2 : az2);

            float bx0 = __shfl_sync(fullm, s1.x, src0);
            float by0 = __shfl_sync(fullm, s1.y, src0);
            float bz0 = __shfl_sync(fullm, s1.z, src0);
            float bw0 = __shfl_sync(fullm, s1.w, src0);
            float bx2 = __shfl_sync(fullm, s1.x, src2);
            float by2 = __shfl_sync(fullm, s1.y, src2);
            float bz2 = __shfl_sync(fullm, s1.z, src2);
            float bw2 = __shfl_sync(fullm, s1.w, src2);
            unsigned pb0 = tf32c(odd ? by0 : bx0);
            unsigned pb1 = tf32c(odd ? bw0 : bz0);
            unsigned pb2 = tf32c(odd ? by2 : bx2);
            unsigned pb3 = tf32c(odd ? bw2 : bz2);

#pragma unroll
            for (int ds = 0; ds < 4; ds++) {
                unsigned v0 = tf32c(Vc[(ns * 8 + t) * 40 + ds * 8 + g]);
                unsigned v1 = tf32c(Vc[(ns * 8 + 4 + t) * 40 + ds * 8 + g]);
                mma_tf32(o0[ds], pa0, pa1, pa2, pa3, v0, v1);
                mma_tf32(o1[ds], pb0, pb1, pb2, pb3, v0, v1);
            }
        }
        __syncthreads();
    }

    l00 += __shfl_xor_sync(fullm, l00, 1); l00 += __shfl_xor_sync(fullm, l00, 2);
    l01 += __shfl_xor_sync(fullm, l01, 1); l01 += __shfl_xor_sync(fullm, l01, 2);
    l10 += __shfl_xor_sync(fullm, l10, 1); l10 += __shfl_xor_sync(fullm, l10, 2);
    l11 += __shfl_xor_sync(fullm, l11, 1); l11 += __shfl_xor_sync(fullm, l11, 2);
    float i00 = 1.f / l00, i01 = 1.f / l01;
    float i10 = 1.f / l10, i11 = 1.f / l11;

    float* p0 = out + (size_t)(b * MM + qw + g) * DD + h * 32;
    float* p1 = out + (size_t)(b * MM + qw + g + 8) * DD + h * 32;
#pragma unroll
    for (int ds = 0; ds < 4; ds++) {
        int col = ds * 8 + t * 2;
        *(float2*)(p0 + col) = make_float2(o0[ds].x * i00, o0[ds].y * i00);
        *(float2*)(p1 + col) = make_float2(o0[ds].z * i01, o0[ds].w * i01);
    }
    float* p2 = out + (size_t)(b * MM + qw + 16 + g) * DD + h * 32;
    float* p3 = out + (size_t)(b * MM + qw + 16 + g + 8) * DD + h * 32;
#pragma unroll
    for (int ds = 0; ds < 4; ds++) {
        int col = ds * 8 + t * 2;
        *(float2*)(p2 + col) = make_float2(o1[ds].x * i10, o1[ds].y * i10);
        *(float2*)(p3 + col) = make_float2(o1[ds].z * i11, o1[ds].w * i11);
    }
}

// ---------------- stage2 fat kernel: attention + csc/csr builds ----------------
#define S2_ATTN 256
#define S2_CSC  (S2_ATTN + 48)
#define S2_CSR  (S2_CSC + 1024)
#define S2_TOT  S2_CSR

__global__ void __launch_bounds__(256, 2)
stage2(const float* __restrict__ qkv, float* __restrict__ attn_out,
       const float* __restrict__ inc)
{
    __shared__ float Ksf[2 * KBUF];
    __shared__ float Vsf[2 * VBUF];
    const int bid = blockIdx.x;
    const int tid = threadIdx.x;

    if (bid < S2_ATTN) {
        attn_body(qkv, attn_out, bid >> 2, bid & 3, Ksf, Vsf);
    } else if (bid < S2_CSC) {
        int ge = (bid - S2_ATTN) * 256 + tid;
        int b = ge / EE, e = ge % EE;
        const float* p = inc + (size_t)b * MM * EE + e;
        unsigned short* lst = g_csc_idx + (size_t)ge * CAP;
        int cnt = 0;
        for (int m = 0; m < MM; m++) {
            if (p[(size_t)m * EE] != 0.f) {
                if (cnt < CAP) lst[cnt] = (unsigned short)m;
                cnt++;
            }
        }
        g_csc_cnt[ge] = cnt < CAP ? cnt : CAP;
    } else {
        int wid = ((bid - S2_CSC) * 256 + tid) >> 5;
        int lane = tid & 31;
        const float* p = inc + (size_t)wid * EE;
        unsigned short* lst = g_csr_idx + (size_t)wid * CAP;
        int cnt = 0;
        for (int eb = 0; eb < EE; eb += 32) {
            float v = p[eb + lane];
            unsigned mask = __ballot_sync(0xffffffffu, v != 0.f);
            if (v != 0.f) {
                int pos = cnt + __popc(mask & ((1u << lane) - 1u));
                if (pos < CAP) lst[pos] = (unsigned short)(eb + lane);
            }
            cnt += __popc(mask);
        }
        if (lane == 0) g_csr_cnt[wid] = cnt < CAP ? cnt : CAP;
    }
}

// ---------------- spmm csc + fused exp-sum stats ----------------
// 4 groups (edges) per 256-thr block; blocks never straddle batches (1536 % 4 == 0).
__global__ void __launch_bounds__(256)
spmm_csc(const unsigned short* __restrict__ idx, const int* __restrict__ cnt,
         const float* __restrict__ X, float* __restrict__ O, float* __restrict__ sump)
{
    __shared__ float esum[256];
    const int tid = threadIdx.x;
    esum[tid] = 0.f;
    __syncthreads();

    int g = blockIdx.x * 4 + (tid >> 6);
    int b = (blockIdx.x * 4) / EE;
    int t = tid & 63;
    int c = cnt[g];
    const unsigned short* lst = idx + (size_t)g * CAP;
    const float* Xb = X + (size_t)b * MM * DD + t * 4;
    float4 s = make_float4(0.f, 0.f, 0.f, 0.f);
    float4 s2 = make_float4(0.f, 0.f, 0.f, 0.f);
    int i = 0;
    for (; i + 8 <= c; i += 8) {
        int r0 = lst[i], r1 = lst[i+1], r2 = lst[i+2], r3 = lst[i+3];
        int r4 = lst[i+4], r5 = lst[i+5], r6 = lst[i+6], r7 = lst[i+7];
        float4 v0 = *(const float4*)(Xb + (size_t)r0 * DD);
        float4 v1 = *(const float4*)(Xb + (size_t)r1 * DD);
        float4 v2 = *(const float4*)(Xb + (size_t)r2 * DD);
        float4 v3 = *(const float4*)(Xb + (size_t)r3 * DD);
        float4 v4 = *(const float4*)(Xb + (size_t)r4 * DD);
        float4 v5 = *(const float4*)(Xb + (size_t)r5 * DD);
        float4 v6 = *(const float4*)(Xb + (size_t)r6 * DD);
        float4 v7 = *(const float4*)(Xb + (size_t)r7 * DD);
        s.x += v0.x; s.y += v0.y; s.z += v0.z; s.w += v0.w;
        s2.x += v1.x; s2.y += v1.y; s2.z += v1.z; s2.w += v1.w;
        s.x += v2.x; s.y += v2.y; s.z += v2.z; s.w += v2.w;
        s2.x += v3.x; s2.y += v3.y; s2.z += v3.z; s2.w += v3.w;
        s.x += v4.x; s.y += v4.y; s.z += v4.z; s.w += v4.w;
        s2.x += v5.x; s2.y += v5.y; s2.z += v5.z; s2.w += v5.w;
        s.x += v6.x; s.y += v6.y; s.z += v6.z; s.w += v6.w;
        s2.x += v7.x; s2.y += v7.y; s2.z += v7.z; s2.w += v7.w;
    }
    for (; i < c; i++) {
        int r = lst[i];
        float4 v = *(const float4*)(Xb + (size_t)r * DD);
        s.x += v.x; s.y += v.y; s.z += v.z; s.w += v.w;
    }
    s.x += s2.x; s.y += s2.y; s.z += s2.z; s.w += s2.w;
    *(float4*)(O + (size_t)g * DD + t * 4) = s;

    // fused softmax denominator partials
    atomicAdd(&esum[t * 4 + 0], __expf(s.x));
    atomicAdd(&esum[t * 4 + 1], __expf(s.y));
    atomicAdd(&esum[t * 4 + 2], __expf(s.z));
    atomicAdd(&esum[t * 4 + 3], __expf(s.w));
    __syncthreads();
    atomicAdd(&sump[b * DD + tid], esum[tid]);
}

// ---------------- spmm csr (scaled by 1/(3+av)) ----------------
__global__ void __launch_bounds__(256)
spmm_csr(const unsigned short* __restrict__ idx, const int* __restrict__ cnt,
         const float* __restrict__ X, float* __restrict__ O, const float* __restrict__ sc)
{
    int g = blockIdx.x * 4 + (threadIdx.x >> 6);
    int b = g / MM;
    int t = threadIdx.x & 63;
    int c = cnt[g];
    const unsigned short* lst = idx + (size_t)g * CAP;
    const float* Xb = X + (size_t)b * EE * DD + t * 4;
    float4 s = make_float4(0.f, 0.f, 0.f, 0.f);
    float4 s2 = make_float4(0.f, 0.f, 0.f, 0.f);
    int i = 0;
    for (; i + 8 <= c; i += 8) {
        int r0 = lst[i], r1 = lst[i+1], r2 = lst[i+2], r3 = lst[i+3];
        int r4 = lst[i+4], r5 = lst[i+5], r6 = lst[i+6], r7 = lst[i+7];
        float4 v0 = *(const float4*)(Xb + (size_t)r0 * DD);
        float4 v1 = *(const float4*)(Xb + (size_t)r1 * DD);
        float4 v2 = *(const float4*)(Xb + (size_t)r2 * DD);
        float4 v3 = *(const float4*)(Xb + (size_t)r3 * DD);
        float4 v4 = *(const float4*)(Xb + (size_t)r4 * DD);
        float4 v5 = *(const float4*)(Xb + (size_t)r5 * DD);
        float4 v6 = *(const float4*)(Xb + (size_t)r6 * DD);
        float4 v7 = *(const float4*)(Xb + (size_t)r7 * DD);
        s.x += v0.x; s.y += v0.y; s.z += v0.z; s.w += v0.w;
        s2.x += v1.x; s2.y += v1.y; s2.z += v1.z; s2.w += v1.w;
        s.x += v2.x; s.y += v2.y; s.z += v2.z; s.w += v2.w;
        s2.x += v3.x; s2.y += v3.y; s2.z += v3.z; s2.w += v3.w;
        s.x += v4.x; s.y += v4.y; s.z += v4.z; s.w += v4.w;
        s2.x += v5.x; s2.y += v5.y; s2.z += v5.z; s2.w += v5.w;
        s.x += v6.x; s.y += v6.y; s.z += v6.z; s.w += v6.w;
        s2.x += v7.x; s2.y += v7.y; s2.z += v7.z; s2.w += v7.w;
    }
    for (; i < c; i++) {
        int r = lst[i];
        float4 v = *(const float4*)(Xb + (size_t)r * DD);
        s.x += v.x; s.y += v.y; s.z += v.z; s.w += v.w;
    }
    s.x += s2.x; s.y += s2.y; s.z += s2.z; s.w += s2.w;
    float f = 1.f / (3.f + *sc);
    s.x *= f; s.y *= f; s.z *= f; s.w *= f;
    *(float4*)(O + (size_t)g * DD + t * 4) = s;
}

// ---------------- reductions ----------------
__device__ __forceinline__ float warp_sum(float v) {
#pragma unroll
    for (int o = 16; o > 0; o >>= 1) v += __shfl_down_sync(0xffffffffu, v, o);
    return v;
}

__device__ __forceinline__ float block_sum256(float v, float* red, float* bc) {
    int lane = threadIdx.x & 31, w = threadIdx.x >> 5;
    float t = warp_sum(v);
    if (lane == 0) red[w] = t;
    __syncthreads();
    if (w == 0) {
        float u = (lane < 8) ? red[lane] : 0.f;
#pragma unroll
        for (int o = 4; o > 0; o >>= 1) u += __shfl_down_sync(0xffffffffu, u, o);
        if (lane == 0) *bc = u;
    }
    __syncthreads();
    return *bc;
}

__global__ void ln_edge_kernel(const float* __restrict__ X, const float* __restrict__ g,
                               const float* __restrict__ bb, const float* __restrict__ p_av,
                               float* __restrict__ out_edge)
{
    const int row = blockIdx.x;
    const int d = threadIdx.x;
    __shared__ float red[8];
    __shared__ float bc;

    float x = X[(size_t)row * DD + d];
    float mu = block_sum256(x, red, &bc) * (1.f / DD);
    float dv = x - mu;
    __syncthreads();
    float var = block_sum256(dv * dv, red, &bc) * (1.f / DD);

    float v = dv * rsqrtf(var + LN_EPS) * g[d] + bb[d];
    out_edge[(size_t)row * DD + d] = (3.f + *p_av) * v;
}

__global__ void final_node_kernel(const float* __restrict__ Y, const float* __restrict__ feat,
                                  const float* __restrict__ g, const float* __restrict__ bb,
                                  const float* __restrict__ p_av, const float* __restrict__ p_ae,
                                  float* __restrict__ out)
{
    const int row = blockIdx.x;
    const int d = threadIdx.x;
    __shared__ float red[8];
    __shared__ float bc;

    float y = Y[(size_t)row * DD + d];
    float mu = block_sum256(y, red, &bc) * (1.f / DD);
    float z = y - mu;
    __syncthreads();
    float vr = block_sum256(z * z, red, &bc) * (1.f / DD);

    const float ae = *p_ae, av = *p_av;
    const float gd = g[d], bd = bb[d];
    const float c3 = 3.f + av;
    const float t1 = z * rsqrtf(vr + LN_EPS) * gd + bd;
    const float t2 = 2.f * z * rsqrtf(4.f * vr + LN_EPS) * gd + bd;
    const float t3 = c3 * z * rsqrtf(c3 * c3 * vr + LN_EPS) * gd + bd;

    const float op = 1.f + ae;
    out[(size_t)row * DD + d] =
        op * op * op * feat[(size_t)row * DD + d] +
        (1.f - ae) * (op * op * t1 + op * t2 + t3);
}

// ---------------- host ----------------
extern "C" void kernel_launch(void* const* d_in, const int* in_sizes, int n_in,
                              void* d_out, int out_size)
{
    const float* feat     = (const float*)d_in[0];
    const float* inc      = (const float*)d_in[1];
    const float* vc_Win   = (const float*)d_in[2];
    const float* vc_bin   = (const float*)d_in[3];
    const float* vc_Wout  = (const float*)d_in[4];
    const float* vc_bout  = (const float*)d_in[5];
    const float* vc_Wproj = (const float*)d_in[6];
    const float* vc_g     = (const float*)d_in[7];
    const float* vc_b     = (const float*)d_in[8];
    const float* vc_alpha = (const float*)d_in[9];
    const float* ec_Wproj = (const float*)d_in[14];
    const float* ec_g     = (const float*)d_in[15];
    const float* ec_b     = (const float*)d_in[16];
    const float* ec_alpha = (const float*)d_in[17];

    float *qkv, *attn, *A, *S, *Ep, *Y1, *Y, *sump;
    unsigned short *csc_idx, *csr_idx;
    int *csc_cnt, *csr_cnt;
    cudaGetSymbolAddress((void**)&qkv,  g_qkv);
    cudaGetSymbolAddress((void**)&attn, g_attn);
    cudaGetSymbolAddress((void**)&A,    g_A);
    cudaGetSymbolAddress((void**)&S,    g_S);
    cudaGetSymbolAddress((void**)&Ep,   g_Ep);
    cudaGetSymbolAddress((void**)&Y1,   g_Y1);
    cudaGetSymbolAddress((void**)&Y,    g_Y);
    cudaGetSymbolAddress((void**)&sump, g_sum);
    cudaGetSymbolAddress((void**)&csc_idx, g_csc_idx);
    cudaGetSymbolAddress((void**)&csr_idx, g_csr_idx);
    cudaGetSymbolAddress((void**)&csc_cnt, g_csc_cnt);
    cudaGetSymbolAddress((void**)&csr_cnt, g_csr_cnt);

    const int NODE = BB * MM * DD;
    const int EDGE = BB * EE * DD;
    const int INC  = BB * MM * EE;
    float* out_node = (float*)d_out;
    float* out_edge = out_node + NODE;
    float* out_inc  = out_edge + EDGE;
    const int do_copy = (out_size >= NODE + EDGE + INC) ? 1 : 0;

    // 1) QKV gemm + inc copy + g_sum zero
    stage1<<<T1_TOT, 256>>>(feat, vc_Win, vc_bin, qkv, inc, out_inc, do_copy);

    // 2) attention + csc/csr index builds
    stage2<<<S2_TOT, 256>>>(qkv, attn, inc);

    // 3) A = attn @ vc_Wout^T + vc_bout
    gemm_mma<true, false><<<dim3(2, 64), 256>>>(attn, vc_Wout, vc_bout, A, 256, 256, nullptr);

    // 4) S = inc^T-gather(A), fused exp-column-sums into g_sum
    spmm_csc<<<BB * EE / 4, 256>>>(csc_idx, csc_cnt, A, S, sump);

    // 5) Ep = (S * exp(S) / colsum) @ vc_Wproj^T
    gemm_mma<false, true><<<dim3(2, 96), 256>>>(S, vc_Wproj, nullptr, Ep, 256, 256, sump);

    // 6) out_edge = (3+av) * LN(Ep)
    ln_edge_kernel<<<BB * EE, DD>>>(Ep, vc_g, vc_b, vc_alpha, out_edge);

    // 7) Y1 = inc-gather(out_edge) / (3+av)
    spmm_csr<<<BB * MM / 4, 256>>>(csr_idx, csr_cnt, out_edge, Y1, vc_alpha);

    // 8) Y = Y1 @ ec_Wproj^T
    gemm_mma<false, false><<<dim3(2, 64), 256>>>(Y1, ec_Wproj, nullptr, Y, 256, 256, nullptr);

    // 9) node output
    final_node_kernel<<<BB * MM, DD>>>(Y, feat, ec_g, ec_b, vc_alpha, ec_alpha, out_node);
}

// round 11
// speedup vs baseline: 1.0070x; 1.0070x over previous
#include <cuda_runtime.h>
#include <math.h>

#define BB 8
#define MM 1024
#define EE 1536
#define DD 256
#define HH 8
#define LN_EPS 1e-5f
#define CAP 256

// ---------------- scratch ----------------
__device__ float g_qkv[BB*MM*3*DD];
__device__ float g_attn[BB*MM*DD];
__device__ float g_A[BB*MM*DD];
__device__ float g_S[BB*EE*DD];
__device__ float g_Ep[BB*EE*DD];
__device__ float g_Y1[BB*MM*DD];
__device__ float g_Y[BB*MM*DD];
__device__ float g_sum[BB*DD];          // column sums of exp(S), atomically accumulated
__device__ unsigned short g_csc_idx[(size_t)BB*EE*CAP];
__device__ int            g_csc_cnt[BB*EE];
__device__ unsigned short g_csr_idx[(size_t)BB*MM*CAP];
__device__ int            g_csr_cnt[BB*MM];

// ---------------- tf32 mma helpers ----------------
__device__ __forceinline__ unsigned tf32c(float f) {
    unsigned r;
    asm("cvt.rna.tf32.f32 %0, %1;" : "=r"(r) : "f"(f));
    return r;
}
__device__ __forceinline__ void mma_tf32(float4& d, unsigned a0, unsigned a1,
                                         unsigned a2, unsigned a3,
                                         unsigned b0, unsigned b1) {
    asm volatile(
        "mma.sync.aligned.m16n8k8.row.col.f32.tf32.tf32.f32 "
        "{%0,%1,%2,%3}, {%4,%5,%6,%7}, {%8,%9}, {%0,%1,%2,%3};"
        : "+f"(d.x), "+f"(d.y), "+f"(d.z), "+f"(d.w)
        : "r"(a0), "r"(a1), "r"(a2), "r"(a3), "r"(b0), "r"(b1));
}

// ---------------- dense GEMM body: C = A[M,K] @ W[N,K]^T (+bias) ----------------
// SOFTW: A-load computes  a = S * exp(S) / colsum[b][k]
template<bool BIAS, bool SOFTW>
__device__ __forceinline__ void
gemm_body(const float* __restrict__ A, const float* __restrict__ W,
          const float* __restrict__ bias, float* __restrict__ C,
          int Ndim, int Kdim, const float* __restrict__ sump,
          int bx, int by)
{
    const int m0 = by * 128;
    const int n0 = bx * 128;
    const int tid = threadIdx.x;
    const int warp = tid >> 5, lane = tid & 31;
    const int wr = warp >> 2, wc = warp & 3;
    const int g = lane >> 2, t = lane & 3;
    const int bb0 = m0 / EE;

    __shared__ unsigned As[128 * 36];
    __shared__ unsigned Bs[128 * 36];
    __shared__ float sinv[256];

    if (SOFTW) {
        sinv[tid] = 1.f / sump[bb0 * DD + tid];
        __syncthreads();
    }

    float4 acc[4][4];
#pragma unroll
    for (int i = 0; i < 4; i++)
#pragma unroll
        for (int j = 0; j < 4; j++) acc[i][j] = make_float4(0.f, 0.f, 0.f, 0.f);

    const int lr = tid >> 3;
    const int lc = (tid & 7) * 4;

    for (int kt = 0; kt < Kdim; kt += 32) {
#pragma unroll
        for (int p = 0; p < 4; p++) {
            int r = lr + p * 32;
            float4 va = *(const float4*)(A + (size_t)(m0 + r) * Kdim + kt + lc);
            if (SOFTW) {
                va.x = va.x * __expf(va.x) * sinv[kt + lc];
                va.y = va.y * __expf(va.y) * sinv[kt + lc + 1];
                va.z = va.z * __expf(va.z) * sinv[kt + lc + 2];
                va.w = va.w * __expf(va.w) * sinv[kt + lc + 3];
            }
            float4 vb = *(const float4*)(W + (size_t)(n0 + r) * Kdim + kt + lc);
            uint4 ua = make_uint4(tf32c(va.x), tf32c(va.y), tf32c(va.z), tf32c(va.w));
            uint4 ub = make_uint4(tf32c(vb.x), tf32c(vb.y), tf32c(vb.z), tf32c(vb.w));
            *(uint4*)&As[r * 36 + lc] = ua;
            *(uint4*)&Bs[r * 36 + lc] = ub;
        }
        __syncthreads();
#pragma unroll
        for (int ks = 0; ks < 4; ks++) {
            const int k0 = ks * 8;
            unsigned af[4][4];
#pragma unroll
            for (int ms = 0; ms < 4; ms++) {
                int row = wr * 64 + ms * 16 + g;
                af[ms][0] = As[row * 36 + k0 + t];
                af[ms][1] = As[(row + 8) * 36 + k0 + t];
                af[ms][2] = As[row * 36 + k0 + 4 + t];
                af[ms][3] = As[(row + 8) * 36 + k0 + 4 + t];
            }
            unsigned bf[4][2];
#pragma unroll
            for (int ns = 0; ns < 4; ns++) {
                int nrow = wc * 32 + ns * 8 + g;
                bf[ns][0] = Bs[nrow * 36 + k0 + t];
                bf[ns][1] = Bs[nrow * 36 + k0 + 4 + t];
            }
#pragma unroll
            for (int ms = 0; ms < 4; ms++)
#pragma unroll
                for (int ns = 0; ns < 4; ns++)
                    mma_tf32(acc[ms][ns], af[ms][0], af[ms][1], af[ms][2], af[ms][3],
                             bf[ns][0], bf[ns][1]);
        }
        __syncthreads();
    }

#pragma unroll
    for (int ms = 0; ms < 4; ms++) {
        int r0 = m0 + wr * 64 + ms * 16 + g;
#pragma unroll
        for (int ns = 0; ns < 4; ns++) {
            int col = n0 + wc * 32 + ns * 8 + t * 2;
            float bx2 = 0.f, by2 = 0.f;
            if (BIAS) { bx2 = bias[col]; by2 = bias[col + 1]; }
            float2 v0 = make_float2(acc[ms][ns].x + bx2, acc[ms][ns].y + by2);
            float2 v1 = make_float2(acc[ms][ns].z + bx2, acc[ms][ns].w + by2);
            *(float2*)(C + (size_t)r0 * Ndim + col)       = v0;
            *(float2*)(C + (size_t)(r0 + 8) * Ndim + col) = v1;
        }
    }
}

template<bool BIAS, bool SOFTW>
__global__ void __launch_bounds__(256)
gemm_mma(const float* __restrict__ A, const float* __restrict__ W,
         const float* __restrict__ bias, float* __restrict__ C,
         int Ndim, int Kdim, const float* __restrict__ sump)
{
    gemm_body<BIAS, SOFTW>(A, W, bias, C, Ndim, Kdim, sump, blockIdx.x, blockIdx.y);
}

// ---------------- stage1 fat kernel: QKV gemm + inc copy + g_sum zero ----------------
#define T1_GEMM 384
#define T1_COPY (T1_GEMM + 1024)
#define T1_TOT  (T1_COPY + 1)

__global__ void __launch_bounds__(256)
stage1(const float* __restrict__ feat, const float* __restrict__ Win,
       const float* __restrict__ bin, float* __restrict__ qkv,
       const float* __restrict__ inc, float* __restrict__ out_inc, int do_copy)
{
    const int bid = blockIdx.x;
    const int tid = threadIdx.x;
    if (bid < T1_GEMM) {
        gemm_body<true, false>(feat, Win, bin, qkv, 768, 256, nullptr, bid % 6, bid / 6);
    } else if (bid < T1_COPY) {
        if (do_copy) {
            const int n4 = BB * MM * EE / 4;
            const int stride = 1024 * 256;
            for (int i = (bid - T1_GEMM) * 256 + tid; i < n4; i += stride)
                ((float4*)out_inc)[i] = ((const float4*)inc)[i];
        }
    } else {
        for (int i = tid; i < BB * DD; i += 256) g_sum[i] = 0.f;
    }
}

// ---------------- attention body (R7 champion version: LDG staging, cvt at staging) ----
__device__ __forceinline__ void
attn_body(const float* __restrict__ qkv, float* __restrict__ out,
          int bh, int qt, unsigned* Ks, unsigned* Vs)
{
    const int b = bh >> 3, h = bh & 7;
    const int tid = threadIdx.x;
    const int warp = tid >> 5, lane = tid & 31;
    const int g = lane >> 2, t = lane & 3;
    const int qw = qt * 256 + warp * 32;

    const float scale = 0.17677669529663687f;
    unsigned qf[2][4][4];
#pragma unroll
    for (int q2 = 0; q2 < 2; q2++) {
        const float* q0 = qkv + (size_t)(b * MM + qw + q2 * 16 + g) * 768 + h * 32;
        const float* q1 = qkv + (size_t)(b * MM + qw + q2 * 16 + g + 8) * 768 + h * 32;
#pragma unroll
        for (int ks = 0; ks < 4; ks++) {
            qf[q2][ks][0] = tf32c(q0[ks * 8 + t] * scale);
            qf[q2][ks][1] = tf32c(q1[ks * 8 + t] * scale);
            qf[q2][ks][2] = tf32c(q0[ks * 8 + 4 + t] * scale);
            qf[q2][ks][3] = tf32c(q1[ks * 8 + 4 + t] * scale);
        }
    }

    float4 o0[4], o1[4];
#pragma unroll
    for (int i = 0; i < 4; i++) {
        o0[i] = make_float4(0.f, 0.f, 0.f, 0.f);
        o1[i] = make_float4(0.f, 0.f, 0.f, 0.f);
    }
    float l00 = 0.f, l01 = 0.f, l10 = 0.f, l11 = 0.f;

    const int lr = tid >> 3;
    const int lc = (tid & 7) * 4;
    const unsigned fullm = 0xffffffffu;
    const int src0 = (lane & 28) | (t >> 1);
    const int src2 = src0 + 2;
    const bool odd = (t & 1);

    for (int ch = 0; ch < 16; ch++) {
        const int kbase = ch * 64;
#pragma unroll
        for (int p = 0; p < 2; p++) {
            int r = lr + p * 32;
            const float* src = qkv + (size_t)(b * MM + kbase + r) * 768 + h * 32 + lc;
            float4 vk = *(const float4*)(src + 256);
            float4 vv = *(const float4*)(src + 512);
            *(uint4*)&Ks[r * 36 + lc] = make_uint4(tf32c(vk.x), tf32c(vk.y), tf32c(vk.z), tf32c(vk.w));
            *(uint4*)&Vs[r * 40 + lc] = make_uint4(tf32c(vv.x), tf32c(vv.y), tf32c(vv.z), tf32c(vv.w));
        }
        __syncthreads();

#pragma unroll
        for (int ns = 0; ns < 8; ns++) {
            float4 s0 = make_float4(0.f, 0.f, 0.f, 0.f);
            float4 s1 = make_float4(0.f, 0.f, 0.f, 0.f);
#pragma unroll
            for (int ks = 0; ks < 4; ks++) {
                int nrow = ns * 8 + g;
                unsigned b0 = Ks[nrow * 36 + ks * 8 + t];
                unsigned b1 = Ks[nrow * 36 + ks * 8 + 4 + t];
                mma_tf32(s0, qf[0][ks][0], qf[0][ks][1], qf[0][ks][2], qf[0][ks][3], b0, b1);
                mma_tf32(s1, qf[1][ks][0], qf[1][ks][1], qf[1][ks][2], qf[1][ks][3], b0, b1);
            }
            s0.x = __expf(s0.x); s0.y = __expf(s0.y); s0.z = __expf(s0.z); s0.w = __expf(s0.w);
            s1.x = __expf(s1.x); s1.y = __expf(s1.y); s1.z = __expf(s1.z); s1.w = __expf(s1.w);
            l00 += s0.x + s0.y; l01 += s0.z + s0.w;
            l10 += s1.x + s1.y; l11 += s1.z + s1.w;

            float ax0 = __shfl_sync(fullm, s0.x, src0);
            float ay0 = __shfl_sync(fullm, s0.y, src0);
            float az0 = __shfl_sync(fullm, s0.z, src0);
            float aw0 = __shfl_sync(fullm, s0.w, src0);
            float ax2 = __shfl_sync(fullm, s0.x, src2);
            float ay2 = __shfl_sync(fullm, s0.y, src2);
            float az2 = __shfl_sync(fullm, s0.z, src2);
            float aw2 = __shfl_sync(fullm, s0.w, src2);
            unsigned pa0 = tf32c(odd ? ay0 : ax0);
            unsigned pa1 = tf32c(odd ? aw0 : az0);
            unsigned pa2 = tf32c(odd ? ay2 : ax2);
            unsigned pa3 = tf32c(odd ? aw2 : az2);

            float bx0 = __shfl_sync(fullm, s1.x, src0);
            float by0 = __shfl_sync(fullm, s1.y, src0);
            float bz0 = __shfl_sync(fullm, s1.z, src0);
            float bw0 = __shfl_sync(fullm, s1.w, src0);
            float bx2 = __shfl_sync(fullm, s1.x, src2);
            float by2 = __shfl_sync(fullm, s1.y, src2);
            float bz2 = __shfl_sync(fullm, s1.z, src2);
            float bw2 = __shfl_sync(fullm, s1.w, src2);
            unsigned pb0 = tf32c(odd ? by0 : bx0);
            unsigned pb1 = tf32c(odd ? bw0 : bz0);
            unsigned pb2 = tf32c(odd ? by2 : bx2);
            unsigned pb3 = tf32c(odd ? bw2 : bz2);

#pragma unroll
            for (int ds = 0; ds < 4; ds++) {
                unsigned v0 = Vs[(ns * 8 + t) * 40 + ds * 8 + g];
                unsigned v1 = Vs[(ns * 8 + 4 + t) * 40 + ds * 8 + g];
                mma_tf32(o0[ds], pa0, pa1, pa2, pa3, v0, v1);
                mma_tf32(o1[ds], pb0, pb1, pb2, pb3, v0, v1);
            }
        }
        __syncthreads();
    }

    l00 += __shfl_xor_sync(fullm, l00, 1); l00 += __shfl_xor_sync(fullm, l00, 2);
    l01 += __shfl_xor_sync(fullm, l01, 1); l01 += __shfl_xor_sync(fullm, l01, 2);
    l10 += __shfl_xor_sync(fullm, l10, 1); l10 += __shfl_xor_sync(fullm, l10, 2);
    l11 += __shfl_xor_sync(fullm, l11, 1); l11 += __shfl_xor_sync(fullm, l11, 2);
    float i00 = 1.f / l00, i01 = 1.f / l01;
    float i10 = 1.f / l10, i11 = 1.f / l11;

    float* p0 = out + (size_t)(b * MM + qw + g) * DD + h * 32;
    float* p1 = out + (size_t)(b * MM + qw + g + 8) * DD + h * 32;
#pragma unroll
    for (int ds = 0; ds < 4; ds++) {
        int col = ds * 8 + t * 2;
        *(float2*)(p0 + col) = make_float2(o0[ds].x * i00, o0[ds].y * i00);
        *(float2*)(p1 + col) = make_float2(o0[ds].z * i01, o0[ds].w * i01);
    }
    float* p2 = out + (size_t)(b * MM + qw + 16 + g) * DD + h * 32;
    float* p3 = out + (size_t)(b * MM + qw + 16 + g + 8) * DD + h * 32;
#pragma unroll
    for (int ds = 0; ds < 4; ds++) {
        int col = ds * 8 + t * 2;
        *(float2*)(p2 + col) = make_float2(o1[ds].x * i10, o1[ds].y * i10);
        *(float2*)(p3 + col) = make_float2(o1[ds].z * i11, o1[ds].w * i11);
    }
}

// ---------------- stage2 fat kernel: attention + csc/csr builds ----------------
#define S2_ATTN 256
#define S2_CSC  (S2_ATTN + 48)
#define S2_CSR  (S2_CSC + 1024)
#define S2_TOT  S2_CSR

__global__ void __launch_bounds__(256, 2)
stage2(const float* __restrict__ qkv, float* __restrict__ attn_out,
       const float* __restrict__ inc)
{
    __shared__ unsigned sh[64 * 36 + 64 * 40];
    const int bid = blockIdx.x;
    const int tid = threadIdx.x;

    if (bid < S2_ATTN) {
        attn_body(qkv, attn_out, bid >> 2, bid & 3, sh, sh + 64 * 36);
    } else if (bid < S2_CSC) {
        int ge = (bid - S2_ATTN) * 256 + tid;
        int b = ge / EE, e = ge % EE;
        const float* p = inc + (size_t)b * MM * EE + e;
        unsigned short* lst = g_csc_idx + (size_t)ge * CAP;
        int cnt = 0;
        for (int m = 0; m < MM; m++) {
            if (p[(size_t)m * EE] != 0.f) {
                if (cnt < CAP) lst[cnt] = (unsigned short)m;
                cnt++;
            }
        }
        g_csc_cnt[ge] = cnt < CAP ? cnt : CAP;
    } else {
        int wid = ((bid - S2_CSC) * 256 + tid) >> 5;
        int lane = tid & 31;
        const float* p = inc + (size_t)wid * EE;
        unsigned short* lst = g_csr_idx + (size_t)wid * CAP;
        int cnt = 0;
        for (int eb = 0; eb < EE; eb += 32) {
            float v = p[eb + lane];
            unsigned mask = __ballot_sync(0xffffffffu, v != 0.f);
            if (v != 0.f) {
                int pos = cnt + __popc(mask & ((1u << lane) - 1u));
                if (pos < CAP) lst[pos] = (unsigned short)(eb + lane);
            }
            cnt += __popc(mask);
        }
        if (lane == 0) g_csr_cnt[wid] = cnt < CAP ? cnt : CAP;
    }
}

// ---------------- sparse aggregation (unroll 8). SCALE: multiply by 1/(3+*sc) ----------------
template<bool SCALE>
__global__ void __launch_bounds__(256)
spmm_gather(const unsigned short* __restrict__ idx, const int* __restrict__ cnt,
            const float* __restrict__ X, float* __restrict__ O,
            int groups_per_b, int rows_per_b, const float* __restrict__ sc)
{
    int g = blockIdx.x * 4 + (threadIdx.x >> 6);
    int b = g / groups_per_b;
    int t = threadIdx.x & 63;
    int c = cnt[g];
    const unsigned short* lst = idx + (size_t)g * CAP;
    const float* Xb = X + (size_t)b * rows_per_b * DD + t * 4;
    float4 s = make_float4(0.f, 0.f, 0.f, 0.f);
    float4 s2 = make_float4(0.f, 0.f, 0.f, 0.f);
    int i = 0;
    for (; i + 8 <= c; i += 8) {
        int r0 = lst[i], r1 = lst[i+1], r2 = lst[i+2], r3 = lst[i+3];
        int r4 = lst[i+4], r5 = lst[i+5], r6 = lst[i+6], r7 = lst[i+7];
        float4 v0 = *(const float4*)(Xb + (size_t)r0 * DD);
        float4 v1 = *(const float4*)(Xb + (size_t)r1 * DD);
        float4 v2 = *(const float4*)(Xb + (size_t)r2 * DD);
        float4 v3 = *(const float4*)(Xb + (size_t)r3 * DD);
        float4 v4 = *(const float4*)(Xb + (size_t)r4 * DD);
        float4 v5 = *(const float4*)(Xb + (size_t)r5 * DD);
        float4 v6 = *(const float4*)(Xb + (size_t)r6 * DD);
        float4 v7 = *(const float4*)(Xb + (size_t)r7 * DD);
        s.x += v0.x; s.y += v0.y; s.z += v0.z; s.w += v0.w;
        s2.x += v1.x; s2.y += v1.y; s2.z += v1.z; s2.w += v1.w;
        s.x += v2.x; s.y += v2.y; s.z += v2.z; s.w += v2.w;
        s2.x += v3.x; s2.y += v3.y; s2.z += v3.z; s2.w += v3.w;
        s.x += v4.x; s.y += v4.y; s.z += v4.z; s.w += v4.w;
        s2.x += v5.x; s2.y += v5.y; s2.z += v5.z; s2.w += v5.w;
        s.x += v6.x; s.y += v6.y; s.z += v6.z; s.w += v6.w;
        s2.x += v7.x; s2.y += v7.y; s2.z += v7.z; s2.w += v7.w;
    }
    for (; i < c; i++) {
        int r = lst[i];
        float4 v = *(const float4*)(Xb + (size_t)r * DD);
        s.x += v.x; s.y += v.y; s.z += v.z; s.w += v.w;
    }
    s.x += s2.x; s.y += s2.y; s.z += s2.z; s.w += s2.w;
    if (SCALE) {
        float f = 1.f / (3.f + *sc);
        s.x *= f; s.y *= f; s.z *= f; s.w *= f;
    }
    *(float4*)(O + (size_t)g * DD + t * 4) = s;
}

// ---------------- softmax stats: g_sum[b,d] += partial sum_e exp(S[b,e,d]) ----------------
__global__ void softmax_stats(const float* __restrict__ S, float* __restrict__ sump)
{
    const int b = blockIdx.y;
    const int tx = threadIdx.x, ty = threadIdx.y;
    const int d = blockIdx.x * 32 + tx;
    const int e0 = blockIdx.z * (EE / 4);
    __shared__ float sm[32][33];

    const float* Sb = S + (size_t)b * EE * DD + d;
    float sum = 0.f;
    for (int e = e0 + ty; e < e0 + EE / 4; e += 32) sum += __expf(Sb[(size_t)e * DD]);
    sm[ty][tx] = sum; __syncthreads();
    for (int s = 16; s > 0; s >>= 1) {
        if (ty < s) sm[ty][tx] += sm[ty + s][tx];
        __syncthreads();
    }
    if (ty == 0) atomicAdd(&sump[b * DD + d], sm[0][tx]);
}

// ---------------- reductions ----------------
__device__ __forceinline__ float warp_sum(float v) {
#pragma unroll
    for (int o = 16; o > 0; o >>= 1) v += __shfl_down_sync(0xffffffffu, v, o);
    return v;
}

__device__ __forceinline__ float block_sum256(float v, float* red, float* bc) {
    int lane = threadIdx.x & 31, w = threadIdx.x >> 5;
    float t = warp_sum(v);
    if (lane == 0) red[w] = t;
    __syncthreads();
    if (w == 0) {
        float u = (lane < 8) ? red[lane] : 0.f;
#pragma unroll
        for (int o = 4; o > 0; o >>= 1) u += __shfl_down_sync(0xffffffffu, u, o);
        if (lane == 0) *bc = u;
    }
    __syncthreads();
    return *bc;
}

__global__ void ln_edge_kernel(const float* __restrict__ X, const float* __restrict__ g,
                               const float* __restrict__ bb, const float* __restrict__ p_av,
                               float* __restrict__ out_edge)
{
    const int row = blockIdx.x;
    const int d = threadIdx.x;
    __shared__ float red[8];
    __shared__ float bc;

    float x = X[(size_t)row * DD + d];
    float mu = block_sum256(x, red, &bc) * (1.f / DD);
    float dv = x - mu;
    __syncthreads();
    float var = block_sum256(dv * dv, red, &bc) * (1.f / DD);

    float v = dv * rsqrtf(var + LN_EPS) * g[d] + bb[d];
    out_edge[(size_t)row * DD + d] = (3.f + *p_av) * v;
}

__global__ void final_node_kernel(const float* __restrict__ Y, const float* __restrict__ feat,
                                  const float* __restrict__ g, const float* __restrict__ bb,
                                  const float* __restrict__ p_av, const float* __restrict__ p_ae,
                                  float* __restrict__ out)
{
    const int row = blockIdx.x;
    const int d = threadIdx.x;
    __shared__ float red[8];
    __shared__ float bc;

    float y = Y[(size_t)row * DD + d];
    float mu = block_sum256(y, red, &bc) * (1.f / DD);
    float z = y - mu;
    __syncthreads();
    float vr = block_sum256(z * z, red, &bc) * (1.f / DD);

    const float ae = *p_ae, av = *p_av;
    const float gd = g[d], bd = bb[d];
    const float c3 = 3.f + av;
    const float t1 = z * rsqrtf(vr + LN_EPS) * gd + bd;
    const float t2 = 2.f * z * rsqrtf(4.f * vr + LN_EPS) * gd + bd;
    const float t3 = c3 * z * rsqrtf(c3 * c3 * vr + LN_EPS) * gd + bd;

    const float op = 1.f + ae;
    out[(size_t)row * DD + d] =
        op * op * op * feat[(size_t)row * DD + d] +
        (1.f - ae) * (op * op * t1 + op * t2 + t3);
}

// ---------------- host ----------------
extern "C" void kernel_launch(void* const* d_in, const int* in_sizes, int n_in,
                              void* d_out, int out_size)
{
    const float* feat     = (const float*)d_in[0];
    const float* inc      = (const float*)d_in[1];
    const float* vc_Win   = (const float*)d_in[2];
    const float* vc_bin   = (const float*)d_in[3];
    const float* vc_Wout  = (const float*)d_in[4];
    const float* vc_bout  = (const float*)d_in[5];
    const float* vc_Wproj = (const float*)d_in[6];
    const float* vc_g     = (const float*)d_in[7];
    const float* vc_b     = (const float*)d_in[8];
    const float* vc_alpha = (const float*)d_in[9];
    const float* ec_Wproj = (const float*)d_in[14];
    const float* ec_g     = (const float*)d_in[15];
    const float* ec_b     = (const float*)d_in[16];
    const float* ec_alpha = (const float*)d_in[17];

    float *qkv, *attn, *A, *S, *Ep, *Y1, *Y, *sump;
    unsigned short *csc_idx, *csr_idx;
    int *csc_cnt, *csr_cnt;
    cudaGetSymbolAddress((void**)&qkv,  g_qkv);
    cudaGetSymbolAddress((void**)&attn, g_attn);
    cudaGetSymbolAddress((void**)&A,    g_A);
    cudaGetSymbolAddress((void**)&S,    g_S);
    cudaGetSymbolAddress((void**)&Ep,   g_Ep);
    cudaGetSymbolAddress((void**)&Y1,   g_Y1);
    cudaGetSymbolAddress((void**)&Y,    g_Y);
    cudaGetSymbolAddress((void**)&sump, g_sum);
    cudaGetSymbolAddress((void**)&csc_idx, g_csc_idx);
    cudaGetSymbolAddress((void**)&csr_idx, g_csr_idx);
    cudaGetSymbolAddress((void**)&csc_cnt, g_csc_cnt);
    cudaGetSymbolAddress((void**)&csr_cnt, g_csr_cnt);

    const int NODE = BB * MM * DD;
    const int EDGE = BB * EE * DD;
    const int INC  = BB * MM * EE;
    float* out_node = (float*)d_out;
    float* out_edge = out_node + NODE;
    float* out_inc  = out_edge + EDGE;
    const int do_copy = (out_size >= NODE + EDGE + INC) ? 1 : 0;

    // 1) QKV gemm + inc copy + g_sum zero (copy/zero overlap the GEMM)
    stage1<<<T1_TOT, 256>>>(feat, vc_Win, vc_bin, qkv, inc, out_inc, do_copy);

    // 2) attention + csc/csr index builds
    stage2<<<S2_TOT, 256>>>(qkv, attn, inc);

    // 3) A = attn @ vc_Wout^T + vc_bout
    gemm_mma<true, false><<<dim3(2, 64), 256>>>(attn, vc_Wout, vc_bout, A, 256, 256, nullptr);

    // 4) S[b,e,:] = sum_m inc[b,m,e] * A[b,m,:]
    spmm_gather<false><<<BB * EE / 4, 256>>>(csc_idx, csc_cnt, A, S, EE, MM, nullptr);

    // 5) g_sum[b,d] = sum_e exp(S)  (4-way e-split, atomic combine)
    softmax_stats<<<dim3(DD / 32, BB, 4), dim3(32, 32)>>>(S, sump);

    // 6) Ep = (S * exp(S) / colsum) @ vc_Wproj^T
    gemm_mma<false, true><<<dim3(2, 96), 256>>>(S, vc_Wproj, nullptr, Ep, 256, 256, sump);

    // 7) out_edge = (3+av) * LN(Ep)
    ln_edge_kernel<<<BB * EE, DD>>>(Ep, vc_g, vc_b, vc_alpha, out_edge);

    // 8) Y1 = inc-gather(out_edge) / (3+av)
    spmm_gather<true><<<BB * MM / 4, 256>>>(csr_idx, csr_cnt, out_edge, Y1, MM, EE, vc_alpha);

    // 9) Y = Y1 @ ec_Wproj^T
    gemm_mma<false, false><<<dim3(2, 64), 256>>>(Y1, ec_Wproj, nullptr, Y, 256, 256, nullptr);

    // 10) node output
    final_node_kernel<<<BB * MM, DD>>>(Y, feat, ec_g, ec_b, vc_alpha, ec_alpha, out_node);
}

// round 12
// speedup vs baseline: 1.1483x; 1.1403x over previous
#include <cuda_runtime.h>
#include <math.h>

#define BB 8
#define MM 1024
#define EE 1536
#define DD 256
#define HH 8
#define LN_EPS 1e-5f
#define CAP 256

// ---------------- scratch ----------------
__device__ float g_qkv[BB*MM*3*DD];
__device__ float g_attn[BB*MM*DD];
__device__ float g_A[BB*MM*DD];
__device__ float g_S[BB*EE*DD];
__device__ float g_Y1[BB*MM*DD];
__device__ float g_sum[BB*DD];
__device__ unsigned short g_csc_idx[(size_t)BB*EE*CAP];
__device__ int            g_csc_cnt[BB*EE];
__device__ unsigned short g_csr_idx[(size_t)BB*MM*CAP];
__device__ int            g_csr_cnt[BB*MM];

// ---------------- tf32 mma helpers ----------------
__device__ __forceinline__ unsigned tf32c(float f) {
    unsigned r;
    asm("cvt.rna.tf32.f32 %0, %1;" : "=r"(r) : "f"(f));
    return r;
}
__device__ __forceinline__ void mma_tf32(float4& d, unsigned a0, unsigned a1,
                                         unsigned a2, unsigned a3,
                                         unsigned b0, unsigned b1) {
    asm volatile(
        "mma.sync.aligned.m16n8k8.row.col.f32.tf32.tf32.f32 "
        "{%0,%1,%2,%3}, {%4,%5,%6,%7}, {%8,%9}, {%0,%1,%2,%3};"
        : "+f"(d.x), "+f"(d.y), "+f"(d.z), "+f"(d.w)
        : "r"(a0), "r"(a1), "r"(a2), "r"(a3), "r"(b0), "r"(b1));
}

// ---------------- standard dense GEMM (128x128 tile): C = A @ W^T (+bias) ----------------
template<bool BIAS>
__global__ void __launch_bounds__(256)
gemm_mma(const float* __restrict__ A, const float* __restrict__ W,
         const float* __restrict__ bias, float* __restrict__ C,
         int Ndim, int Kdim)
{
    const int m0 = blockIdx.y * 128;
    const int n0 = blockIdx.x * 128;
    const int tid = threadIdx.x;
    const int warp = tid >> 5, lane = tid & 31;
    const int wr = warp >> 2, wc = warp & 3;
    const int g = lane >> 2, t = lane & 3;

    __shared__ unsigned As[128 * 36];
    __shared__ unsigned Bs[128 * 36];

    float4 acc[4][4];
#pragma unroll
    for (int i = 0; i < 4; i++)
#pragma unroll
        for (int j = 0; j < 4; j++) acc[i][j] = make_float4(0.f, 0.f, 0.f, 0.f);

    const int lr = tid >> 3;
    const int lc = (tid & 7) * 4;

    for (int kt = 0; kt < Kdim; kt += 32) {
#pragma unroll
        for (int p = 0; p < 4; p++) {
            int r = lr + p * 32;
            float4 va = *(const float4*)(A + (size_t)(m0 + r) * Kdim + kt + lc);
            float4 vb = *(const float4*)(W + (size_t)(n0 + r) * Kdim + kt + lc);
            *(uint4*)&As[r * 36 + lc] = make_uint4(tf32c(va.x), tf32c(va.y), tf32c(va.z), tf32c(va.w));
            *(uint4*)&Bs[r * 36 + lc] = make_uint4(tf32c(vb.x), tf32c(vb.y), tf32c(vb.z), tf32c(vb.w));
        }
        __syncthreads();
#pragma unroll
        for (int ks = 0; ks < 4; ks++) {
            const int k0 = ks * 8;
            unsigned af[4][4];
#pragma unroll
            for (int ms = 0; ms < 4; ms++) {
                int row = wr * 64 + ms * 16 + g;
                af[ms][0] = As[row * 36 + k0 + t];
                af[ms][1] = As[(row + 8) * 36 + k0 + t];
                af[ms][2] = As[row * 36 + k0 + 4 + t];
                af[ms][3] = As[(row + 8) * 36 + k0 + 4 + t];
            }
            unsigned bf[4][2];
#pragma unroll
            for (int ns = 0; ns < 4; ns++) {
                int nrow = wc * 32 + ns * 8 + g;
                bf[ns][0] = Bs[nrow * 36 + k0 + t];
                bf[ns][1] = Bs[nrow * 36 + k0 + 4 + t];
            }
#pragma unroll
            for (int ms = 0; ms < 4; ms++)
#pragma unroll
                for (int ns = 0; ns < 4; ns++)
                    mma_tf32(acc[ms][ns], af[ms][0], af[ms][1], af[ms][2], af[ms][3],
                             bf[ns][0], bf[ns][1]);
        }
        __syncthreads();
    }

#pragma unroll
    for (int ms = 0; ms < 4; ms++) {
        int r0 = m0 + wr * 64 + ms * 16 + g;
#pragma unroll
        for (int ns = 0; ns < 4; ns++) {
            int col = n0 + wc * 32 + ns * 8 + t * 2;
            float bx2 = 0.f, by2 = 0.f;
            if (BIAS) { bx2 = bias[col]; by2 = bias[col + 1]; }
            *(float2*)(C + (size_t)r0 * Ndim + col)       = make_float2(acc[ms][ns].x + bx2, acc[ms][ns].y + by2);
            *(float2*)(C + (size_t)(r0 + 8) * Ndim + col) = make_float2(acc[ms][ns].z + bx2, acc[ms][ns].w + by2);
        }
    }
}

// ---------------- full-N GEMM with fused row-LN epilogue ----------------
// tile: 64 rows x 256 cols (full N), 8 warps each 64x32. K = 256.
// SOFTW: A-load computes a = S*exp(S)/colsum.
// EPI=1: out = (3+av) * LN(row)            (edge output)
// EPI=2: out = op^3*feat + (1-ae)*(op^2*t1 + op*t2 + t3)   (node output)
template<bool SOFTW, int EPI>
__global__ void __launch_bounds__(256)
gemm_epi(const float* __restrict__ A, const float* __restrict__ W,
         float* __restrict__ out, const float* __restrict__ sump,
         const float* __restrict__ gvec, const float* __restrict__ bvec,
         const float* __restrict__ p_av, const float* __restrict__ p_ae,
         const float* __restrict__ feat)
{
    const int m0 = blockIdx.x * 64;
    const int tid = threadIdx.x;
    const int warp = tid >> 5, lane = tid & 31;
    const int g = lane >> 2, t = lane & 3;
    const int bb0 = m0 / EE;    // batch (SOFTW only; 1536 % 64 == 0)

    __shared__ unsigned As[64 * 36];     // 9216 B; reused post-loop for reductions
    __shared__ unsigned Bs[256 * 36];    // 36864 B
    __shared__ float sinv[256];          // 1024 B

    if (SOFTW) {
        sinv[tid] = 1.f / sump[bb0 * DD + tid];
        __syncthreads();
    }

    float4 acc[4][4];
#pragma unroll
    for (int i = 0; i < 4; i++)
#pragma unroll
        for (int j = 0; j < 4; j++) acc[i][j] = make_float4(0.f, 0.f, 0.f, 0.f);

    const int lr = tid >> 3;          // 0..31
    const int lc = (tid & 7) * 4;     // 0..28

    for (int kt = 0; kt < 256; kt += 32) {
#pragma unroll
        for (int p = 0; p < 2; p++) {
            int r = lr + p * 32;
            float4 va = *(const float4*)(A + (size_t)(m0 + r) * 256 + kt + lc);
            if (SOFTW) {
                va.x = va.x * __expf(va.x) * sinv[kt + lc];
                va.y = va.y * __expf(va.y) * sinv[kt + lc + 1];
                va.z = va.z * __expf(va.z) * sinv[kt + lc + 2];
                va.w = va.w * __expf(va.w) * sinv[kt + lc + 3];
            }
            *(uint4*)&As[r * 36 + lc] = make_uint4(tf32c(va.x), tf32c(va.y), tf32c(va.z), tf32c(va.w));
        }
#pragma unroll
        for (int p = 0; p < 8; p++) {
            int r = lr + p * 32;
            float4 vb = *(const float4*)(W + (size_t)r * 256 + kt + lc);
            *(uint4*)&Bs[r * 36 + lc] = make_uint4(tf32c(vb.x), tf32c(vb.y), tf32c(vb.z), tf32c(vb.w));
        }
        __syncthreads();
#pragma unroll
        for (int ks = 0; ks < 4; ks++) {
            const int k0 = ks * 8;
            unsigned af[4][4];
#pragma unroll
            for (int ms = 0; ms < 4; ms++) {
                int row = ms * 16 + g;
                af[ms][0] = As[row * 36 + k0 + t];
                af[ms][1] = As[(row + 8) * 36 + k0 + t];
                af[ms][2] = As[row * 36 + k0 + 4 + t];
                af[ms][3] = As[(row + 8) * 36 + k0 + 4 + t];
            }
            unsigned bf[4][2];
#pragma unroll
            for (int ns = 0; ns < 4; ns++) {
                int nrow = warp * 32 + ns * 8 + g;
                bf[ns][0] = Bs[nrow * 36 + k0 + t];
                bf[ns][1] = Bs[nrow * 36 + k0 + 4 + t];
            }
#pragma unroll
            for (int ms = 0; ms < 4; ms++)
#pragma unroll
                for (int ns = 0; ns < 4; ns++)
                    mma_tf32(acc[ms][ns], af[ms][0], af[ms][1], af[ms][2], af[ms][3],
                             bf[ns][0], bf[ns][1]);
        }
        __syncthreads();
    }

    // ---- fused row-LN epilogue (As reused as scratch; all As reads complete) ----
    float* rowred = (float*)As;            // [64][8][2] = 4096 B
    float* rstat  = (float*)As + 1024;     // [64][2]    =  512 B

    const unsigned fm = 0xffffffffu;
#pragma unroll
    for (int ms = 0; ms < 4; ms++) {
        float s0 = 0.f, q0 = 0.f, s1 = 0.f, q1 = 0.f;
#pragma unroll
        for (int ns = 0; ns < 4; ns++) {
            float4 a = acc[ms][ns];
            s0 += a.x + a.y; q0 += a.x * a.x + a.y * a.y;
            s1 += a.z + a.w; q1 += a.z * a.z + a.w * a.w;
        }
        s0 += __shfl_xor_sync(fm, s0, 1); s0 += __shfl_xor_sync(fm, s0, 2);
        q0 += __shfl_xor_sync(fm, q0, 1); q0 += __shfl_xor_sync(fm, q0, 2);
        s1 += __shfl_xor_sync(fm, s1, 1); s1 += __shfl_xor_sync(fm, s1, 2);
        q1 += __shfl_xor_sync(fm, q1, 1); q1 += __shfl_xor_sync(fm, q1, 2);
        if (t == 0) {
            int r0 = ms * 16 + g, r1 = r0 + 8;
            rowred[(r0 * 8 + warp) * 2]     = s0;
            rowred[(r0 * 8 + warp) * 2 + 1] = q0;
            rowred[(r1 * 8 + warp) * 2]     = s1;
            rowred[(r1 * 8 + warp) * 2 + 1] = q1;
        }
    }
    __syncthreads();
    if (tid < 64) {
        float s = 0.f, q = 0.f;
#pragma unroll
        for (int w = 0; w < 8; w++) {
            s += rowred[(tid * 8 + w) * 2];
            q += rowred[(tid * 8 + w) * 2 + 1];
        }
        float mu = s * (1.f / 256.f);
        float var = q * (1.f / 256.f) - mu * mu;
        // note: write AFTER all reads of rowred by this thread (same region alias-safe: rstat offset 4096B)
        rstat[tid * 2]     = mu;
        rstat[tid * 2 + 1] = var;
    }
    __syncthreads();

    const float av = *p_av;
    if (EPI == 1) {
        const float c = 3.f + av;
#pragma unroll
        for (int ms = 0; ms < 4; ms++) {
            int r0 = ms * 16 + g, r1 = r0 + 8;
            float mu0 = rstat[r0 * 2], rs0 = rsqrtf(rstat[r0 * 2 + 1] + LN_EPS);
            float mu1 = rstat[r1 * 2], rs1 = rsqrtf(rstat[r1 * 2 + 1] + LN_EPS);
#pragma unroll
            for (int ns = 0; ns < 4; ns++) {
                int col = warp * 32 + ns * 8 + t * 2;
                float gx = __ldg(gvec + col), gy = __ldg(gvec + col + 1);
                float bx = __ldg(bvec + col), by = __ldg(bvec + col + 1);
                float4 a = acc[ms][ns];
                *(float2*)(out + (size_t)(m0 + r0) * DD + col) =
                    make_float2(c * ((a.x - mu0) * rs0 * gx + bx),
                                c * ((a.y - mu0) * rs0 * gy + by));
                *(float2*)(out + (size_t)(m0 + r1) * DD + col) =
                    make_float2(c * ((a.z - mu1) * rs1 * gx + bx),
                                c * ((a.w - mu1) * rs1 * gy + by));
            }
        }
    } else {
        const float ae = *p_ae;
        const float op = 1.f + ae;
        const float c3 = 3.f + av;
        const float w3 = op * op * op, w1 = (1.f - ae) * op * op,
                    w2 = (1.f - ae) * op, wz = (1.f - ae);
#pragma unroll
        for (int ms = 0; ms < 4; ms++) {
            int r0 = ms * 16 + g, r1 = r0 + 8;
            float mu0 = rstat[r0 * 2], v0 = rstat[r0 * 2 + 1];
            float mu1 = rstat[r1 * 2], v1 = rstat[r1 * 2 + 1];
            float ra0 = rsqrtf(v0 + LN_EPS), rb0 = 2.f * rsqrtf(4.f * v0 + LN_EPS),
                  rc0 = c3 * rsqrtf(c3 * c3 * v0 + LN_EPS);
            float ra1 = rsqrtf(v1 + LN_EPS), rb1 = 2.f * rsqrtf(4.f * v1 + LN_EPS),
                  rc1 = c3 * rsqrtf(c3 * c3 * v1 + LN_EPS);
            // coefficient on z*g: w1*ra + w2*rb + wz*rc ; coefficient on b: w1+w2+wz
            float ka0 = w1 * ra0 + w2 * rb0 + wz * rc0;
            float ka1 = w1 * ra1 + w2 * rb1 + wz * rc1;
            float kb = w1 + w2 + wz;
#pragma unroll
            for (int ns = 0; ns < 4; ns++) {
                int col = warp * 32 + ns * 8 + t * 2;
                float gx = __ldg(gvec + col), gy = __ldg(gvec + col + 1);
                float bx = __ldg(bvec + col), by = __ldg(bvec + col + 1);
                float4 a = acc[ms][ns];
                float2 f0 = *(const float2*)(feat + (size_t)(m0 + r0) * DD + col);
                float2 f1 = *(const float2*)(feat + (size_t)(m0 + r1) * DD + col);
                *(float2*)(out + (size_t)(m0 + r0) * DD + col) =
                    make_float2(w3 * f0.x + (a.x - mu0) * ka0 * gx + kb * bx,
                                w3 * f0.y + (a.y - mu0) * ka0 * gy + kb * by);
                *(float2*)(out + (size_t)(m0 + r1) * DD + col) =
                    make_float2(w3 * f1.x + (a.z - mu1) * ka1 * gx + kb * bx,
                                w3 * f1.y + (a.w - mu1) * ka1 * gy + kb * by);
            }
        }
    }
}

// ---------------- attention body (champion version: LDG staging, cvt at staging) ----
__device__ __forceinline__ void
attn_body(const float* __restrict__ qkv, float* __restrict__ out,
          int bh, int qt, unsigned* Ks, unsigned* Vs)
{
    const int b = bh >> 3, h = bh & 7;
    const int tid = threadIdx.x;
    const int warp = tid >> 5, lane = tid & 31;
    const int g = lane >> 2, t = lane & 3;
    const int qw = qt * 256 + warp * 32;

    const float scale = 0.17677669529663687f;
    unsigned qf[2][4][4];
#pragma unroll
    for (int q2 = 0; q2 < 2; q2++) {
        const float* q0 = qkv + (size_t)(b * MM + qw + q2 * 16 + g) * 768 + h * 32;
        const float* q1 = qkv + (size_t)(b * MM + qw + q2 * 16 + g + 8) * 768 + h * 32;
#pragma unroll
        for (int ks = 0; ks < 4; ks++) {
            qf[q2][ks][0] = tf32c(q0[ks * 8 + t] * scale);
            qf[q2][ks][1] = tf32c(q1[ks * 8 + t] * scale);
            qf[q2][ks][2] = tf32c(q0[ks * 8 + 4 + t] * scale);
            qf[q2][ks][3] = tf32c(q1[ks * 8 + 4 + t] * scale);
        }
    }

    float4 o0[4], o1[4];
#pragma unroll
    for (int i = 0; i < 4; i++) {
        o0[i] = make_float4(0.f, 0.f, 0.f, 0.f);
        o1[i] = make_float4(0.f, 0.f, 0.f, 0.f);
    }
    float l00 = 0.f, l01 = 0.f, l10 = 0.f, l11 = 0.f;

    const int lr = tid >> 3;
    const int lc = (tid & 7) * 4;
    const unsigned fullm = 0xffffffffu;
    const int src0 = (lane & 28) | (t >> 1);
    const int src2 = src0 + 2;
    const bool odd = (t & 1);

    for (int ch = 0; ch < 16; ch++) {
        const int kbase = ch * 64;
#pragma unroll
        for (int p = 0; p < 2; p++) {
            int r = lr + p * 32;
            const float* src = qkv + (size_t)(b * MM + kbase + r) * 768 + h * 32 + lc;
            float4 vk = *(const float4*)(src + 256);
            float4 vv = *(const float4*)(src + 512);
            *(uint4*)&Ks[r * 36 + lc] = make_uint4(tf32c(vk.x), tf32c(vk.y), tf32c(vk.z), tf32c(vk.w));
            *(uint4*)&Vs[r * 40 + lc] = make_uint4(tf32c(vv.x), tf32c(vv.y), tf32c(vv.z), tf32c(vv.w));
        }
        __syncthreads();

#pragma unroll
        for (int ns = 0; ns < 8; ns++) {
            float4 s0 = make_float4(0.f, 0.f, 0.f, 0.f);
            float4 s1 = make_float4(0.f, 0.f, 0.f, 0.f);
#pragma unroll
            for (int ks = 0; ks < 4; ks++) {
                int nrow = ns * 8 + g;
                unsigned b0 = Ks[nrow * 36 + ks * 8 + t];
                unsigned b1 = Ks[nrow * 36 + ks * 8 + 4 + t];
                mma_tf32(s0, qf[0][ks][0], qf[0][ks][1], qf[0][ks][2], qf[0][ks][3], b0, b1);
                mma_tf32(s1, qf[1][ks][0], qf[1][ks][1], qf[1][ks][2], qf[1][ks][3], b0, b1);
            }
            s0.x = __expf(s0.x); s0.y = __expf(s0.y); s0.z = __expf(s0.z); s0.w = __expf(s0.w);
            s1.x = __expf(s1.x); s1.y = __expf(s1.y); s1.z = __expf(s1.z); s1.w = __expf(s1.w);
            l00 += s0.x + s0.y; l01 += s0.z + s0.w;
            l10 += s1.x + s1.y; l11 += s1.z + s1.w;

            float ax0 = __shfl_sync(fullm, s0.x, src0);
            float ay0 = __shfl_sync(fullm, s0.y, src0);
            float az0 = __shfl_sync(fullm, s0.z, src0);
            float aw0 = __shfl_sync(fullm, s0.w, src0);
            float ax2 = __shfl_sync(fullm, s0.x, src2);
            float ay2 = __shfl_sync(fullm, s0.y, src2);
            float az2 = __shfl_sync(fullm, s0.z, src2);
            float aw2 = __shfl_sync(fullm, s0.w, src2);
            unsigned pa0 = tf32c(odd ? ay0 : ax0);
            unsigned pa1 = tf32c(odd ? aw0 : az0);
            unsigned pa2 = tf32c(odd ? ay2 : ax2);
            unsigned pa3 = tf32c(odd ? aw2 : az2);

            float bx0 = __shfl_sync(fullm, s1.x, src0);
            float by0 = __shfl_sync(fullm, s1.y, src0);
            float bz0 = __shfl_sync(fullm, s1.z, src0);
            float bw0 = __shfl_sync(fullm, s1.w, src0);
            float bx2 = __shfl_sync(fullm, s1.x, src2);
            float by2 = __shfl_sync(fullm, s1.y, src2);
            float bz2 = __shfl_sync(fullm, s1.z, src2);
            float bw2 = __shfl_sync(fullm, s1.w, src2);
            unsigned pb0 = tf32c(odd ? by0 : bx0);
            unsigned pb1 = tf32c(odd ? bw0 : bz0);
            unsigned pb2 = tf32c(odd ? by2 : bx2);
            unsigned pb3 = tf32c(odd ? bw2 : bz2);

#pragma unroll
            for (int ds = 0; ds < 4; ds++) {
                unsigned v0 = Vs[(ns * 8 + t) * 40 + ds * 8 + g];
                unsigned v1 = Vs[(ns * 8 + 4 + t) * 40 + ds * 8 + g];
                mma_tf32(o0[ds], pa0, pa1, pa2, pa3, v0, v1);
                mma_tf32(o1[ds], pb0, pb1, pb2, pb3, v0, v1);
            }
        }
        __syncthreads();
    }

    l00 += __shfl_xor_sync(fullm, l00, 1); l00 += __shfl_xor_sync(fullm, l00, 2);
    l01 += __shfl_xor_sync(fullm, l01, 1); l01 += __shfl_xor_sync(fullm, l01, 2);
    l10 += __shfl_xor_sync(fullm, l10, 1); l10 += __shfl_xor_sync(fullm, l10, 2);
    l11 += __shfl_xor_sync(fullm, l11, 1); l11 += __shfl_xor_sync(fullm, l11, 2);
    float i00 = 1.f / l00, i01 = 1.f / l01;
    float i10 = 1.f / l10, i11 = 1.f / l11;

    float* p0 = out + (size_t)(b * MM + qw + g) * DD + h * 32;
    float* p1 = out + (size_t)(b * MM + qw + g + 8) * DD + h * 32;
#pragma unroll
    for (int ds = 0; ds < 4; ds++) {
        int col = ds * 8 + t * 2;
        *(float2*)(p0 + col) = make_float2(o0[ds].x * i00, o0[ds].y * i00);
        *(float2*)(p1 + col) = make_float2(o0[ds].z * i01, o0[ds].w * i01);
    }
    float* p2 = out + (size_t)(b * MM + qw + 16 + g) * DD + h * 32;
    float* p3 = out + (size_t)(b * MM + qw + 16 + g + 8) * DD + h * 32;
#pragma unroll
    for (int ds = 0; ds < 4; ds++) {
        int col = ds * 8 + t * 2;
        *(float2*)(p2 + col) = make_float2(o1[ds].x * i10, o1[ds].y * i10);
        *(float2*)(p3 + col) = make_float2(o1[ds].z * i11, o1[ds].w * i11);
    }
}

// ---------------- stage2 fat kernel (champion config): attn + csc + csr + copy + zero ----
#define S2_ATTN 256
#define S2_CSC  (S2_ATTN + 48)
#define S2_CSR  (S2_CSC + 1024)
#define S2_COPY (S2_CSR + 1024)
#define S2_TOT  (S2_COPY + 1)

__global__ void __launch_bounds__(256, 2)
stage2(const float* __restrict__ qkv, float* __restrict__ attn_out,
       const float* __restrict__ inc, float* __restrict__ out_inc, int do_copy)
{
    __shared__ unsigned sh[64 * 36 + 64 * 40];
    const int bid = blockIdx.x;
    const int tid = threadIdx.x;

    if (bid < S2_ATTN) {
        attn_body(qkv, attn_out, bid >> 2, bid & 3, sh, sh + 64 * 36);
    } else if (bid < S2_CSC) {
        int ge = (bid - S2_ATTN) * 256 + tid;
        int b = ge / EE, e = ge % EE;
        const float* p = inc + (size_t)b * MM * EE + e;
        unsigned short* lst = g_csc_idx + (size_t)ge * CAP;
        int cnt = 0;
        for (int m = 0; m < MM; m++) {
            if (p[(size_t)m * EE] != 0.f) {
                if (cnt < CAP) lst[cnt] = (unsigned short)m;
                cnt++;
            }
        }
        g_csc_cnt[ge] = cnt < CAP ? cnt : CAP;
    } else if (bid < S2_CSR) {
        int wid = ((bid - S2_CSC) * 256 + tid) >> 5;
        int lane = tid & 31;
        const float* p = inc + (size_t)wid * EE;
        unsigned short* lst = g_csr_idx + (size_t)wid * CAP;
        int cnt = 0;
        for (int eb = 0; eb < EE; eb += 32) {
            float v = p[eb + lane];
            unsigned mask = __ballot_sync(0xffffffffu, v != 0.f);
            if (v != 0.f) {
                int pos = cnt + __popc(mask & ((1u << lane) - 1u));
                if (pos < CAP) lst[pos] = (unsigned short)(eb + lane);
            }
            cnt += __popc(mask);
        }
        if (lane == 0) g_csr_cnt[wid] = cnt < CAP ? cnt : CAP;
    } else if (bid < S2_COPY) {
        if (do_copy) {
            const int n4 = BB * MM * EE / 4;
            const int stride = 1024 * 256;
            for (int i = (bid - S2_CSR) * 256 + tid; i < n4; i += stride)
                ((float4*)out_inc)[i] = ((const float4*)inc)[i];
        }
    } else {
        for (int i = tid; i < BB * DD; i += 256) g_sum[i] = 0.f;
    }
}

// ---------------- sparse aggregation (unroll 8). SCALE: multiply by 1/(3+*sc) ----------------
template<bool SCALE>
__global__ void __launch_bounds__(256)
spmm_gather(const unsigned short* __restrict__ idx, const int* __restrict__ cnt,
            const float* __restrict__ X, float* __restrict__ O,
            int groups_per_b, int rows_per_b, const float* __restrict__ sc)
{
    int g = blockIdx.x * 4 + (threadIdx.x >> 6);
    int b = g / groups_per_b;
    int t = threadIdx.x & 63;
    int c = cnt[g];
    const unsigned short* lst = idx + (size_t)g * CAP;
    const float* Xb = X + (size_t)b * rows_per_b * DD + t * 4;
    float4 s = make_float4(0.f, 0.f, 0.f, 0.f);
    float4 s2 = make_float4(0.f, 0.f, 0.f, 0.f);
    int i = 0;
    for (; i + 8 <= c; i += 8) {
        int r0 = lst[i], r1 = lst[i+1], r2 = lst[i+2], r3 = lst[i+3];
        int r4 = lst[i+4], r5 = lst[i+5], r6 = lst[i+6], r7 = lst[i+7];
        float4 v0 = *(const float4*)(Xb + (size_t)r0 * DD);
        float4 v1 = *(const float4*)(Xb + (size_t)r1 * DD);
        float4 v2 = *(const float4*)(Xb + (size_t)r2 * DD);
        float4 v3 = *(const float4*)(Xb + (size_t)r3 * DD);
        float4 v4 = *(const float4*)(Xb + (size_t)r4 * DD);
        float4 v5 = *(const float4*)(Xb + (size_t)r5 * DD);
        float4 v6 = *(const float4*)(Xb + (size_t)r6 * DD);
        float4 v7 = *(const float4*)(Xb + (size_t)r7 * DD);
        s.x += v0.x; s.y += v0.y; s.z += v0.z; s.w += v0.w;
        s2.x += v1.x; s2.y += v1.y; s2.z += v1.z; s2.w += v1.w;
        s.x += v2.x; s.y += v2.y; s.z += v2.z; s.w += v2.w;
        s2.x += v3.x; s2.y += v3.y; s2.z += v3.z; s2.w += v3.w;
        s.x += v4.x; s.y += v4.y; s.z += v4.z; s.w += v4.w;
        s2.x += v5.x; s2.y += v5.y; s2.z += v5.z; s2.w += v5.w;
        s.x += v6.x; s.y += v6.y; s.z += v6.z; s.w += v6.w;
        s2.x += v7.x; s2.y += v7.y; s2.z += v7.z; s2.w += v7.w;
    }
    for (; i < c; i++) {
        int r = lst[i];
        float4 v = *(const float4*)(Xb + (size_t)r * DD);
        s.x += v.x; s.y += v.y; s.z += v.z; s.w += v.w;
    }
    s.x += s2.x; s.y += s2.y; s.z += s2.z; s.w += s2.w;
    if (SCALE) {
        float f = 1.f / (3.f + *sc);
        s.x *= f; s.y *= f; s.z *= f; s.w *= f;
    }
    *(float4*)(O + (size_t)g * DD + t * 4) = s;
}

// ---------------- softmax stats: g_sum[b,d] += partial sum_e exp(S[b,e,d]) ----------------
__global__ void softmax_stats(const float* __restrict__ S, float* __restrict__ sump)
{
    const int b = blockIdx.y;
    const int tx = threadIdx.x, ty = threadIdx.y;
    const int d = blockIdx.x * 32 + tx;
    const int e0 = blockIdx.z * (EE / 4);
    __shared__ float sm[32][33];

    const float* Sb = S + (size_t)b * EE * DD + d;
    float sum = 0.f;
    for (int e = e0 + ty; e < e0 + EE / 4; e += 32) sum += __expf(Sb[(size_t)e * DD]);
    sm[ty][tx] = sum; __syncthreads();
    for (int s = 16; s > 0; s >>= 1) {
        if (ty < s) sm[ty][tx] += sm[ty + s][tx];
        __syncthreads();
    }
    if (ty == 0) atomicAdd(&sump[b * DD + d], sm[0][tx]);
}

// ---------------- host ----------------
extern "C" void kernel_launch(void* const* d_in, const int* in_sizes, int n_in,
                              void* d_out, int out_size)
{
    const float* feat     = (const float*)d_in[0];
    const float* inc      = (const float*)d_in[1];
    const float* vc_Win   = (const float*)d_in[2];
    const float* vc_bin   = (const float*)d_in[3];
    const float* vc_Wout  = (const float*)d_in[4];
    const float* vc_bout  = (const float*)d_in[5];
    const float* vc_Wproj = (const float*)d_in[6];
    const float* vc_g     = (const float*)d_in[7];
    const float* vc_b     = (const float*)d_in[8];
    const float* vc_alpha = (const float*)d_in[9];
    const float* ec_Wproj = (const float*)d_in[14];
    const float* ec_g     = (const float*)d_in[15];
    const float* ec_b     = (const float*)d_in[16];
    const float* ec_alpha = (const float*)d_in[17];

    float *qkv, *attn, *A, *S, *Y1, *sump;
    unsigned short *csc_idx, *csr_idx;
    int *csc_cnt, *csr_cnt;
    cudaGetSymbolAddress((void**)&qkv,  g_qkv);
    cudaGetSymbolAddress((void**)&attn, g_attn);
    cudaGetSymbolAddress((void**)&A,    g_A);
    cudaGetSymbolAddress((void**)&S,    g_S);
    cudaGetSymbolAddress((void**)&Y1,   g_Y1);
    cudaGetSymbolAddress((void**)&sump, g_sum);
    cudaGetSymbolAddress((void**)&csc_idx, g_csc_idx);
    cudaGetSymbolAddress((void**)&csr_idx, g_csr_idx);
    cudaGetSymbolAddress((void**)&csc_cnt, g_csc_cnt);
    cudaGetSymbolAddress((void**)&csr_cnt, g_csr_cnt);

    const int NODE = BB * MM * DD;
    const int EDGE = BB * EE * DD;
    const int INC  = BB * MM * EE;
    float* out_node = (float*)d_out;
    float* out_edge = out_node + NODE;
    float* out_inc  = out_edge + EDGE;
    const int do_copy = (out_size >= NODE + EDGE + INC) ? 1 : 0;

    // 1) QKV = feat @ vc_Win^T + vc_bin   (standalone, as in champion)
    gemm_mma<true><<<dim3(6, 64), 256>>>(feat, vc_Win, vc_bin, qkv, 768, 256);

    // 2) fat kernel: attention + csc/csr builds + inc copy + g_sum zero (champion config)
    stage2<<<S2_TOT, 256>>>(qkv, attn, inc, out_inc, do_copy);

    // 3) A = attn @ vc_Wout^T + vc_bout
    gemm_mma<true><<<dim3(2, 64), 256>>>(attn, vc_Wout, vc_bout, A, 256, 256);

    // 4) S[b,e,:] = sum_m inc[b,m,e] * A[b,m,:]
    spmm_gather<false><<<BB * EE / 4, 256>>>(csc_idx, csc_cnt, A, S, EE, MM, nullptr);

    // 5) g_sum[b,d] = sum_e exp(S)  (4-way e-split, atomic combine)
    softmax_stats<<<dim3(DD / 32, BB, 4), dim3(32, 32)>>>(S, sump);

    // 6) out_edge = (3+av) * LN( (S*exp(S)/colsum) @ vc_Wproj^T )   — fused epilogue
    gemm_epi<true, 1><<<BB * EE / 64, 256>>>(S, vc_Wproj, out_edge, sump,
                                             vc_g, vc_b, vc_alpha, nullptr, nullptr);

    // 7) Y1 = inc-gather(out_edge) / (3+av)
    spmm_gather<true><<<BB * MM / 4, 256>>>(csr_idx, csr_cnt, out_edge, Y1, MM, EE, vc_alpha);

    // 8) out_node = node-combine( LN terms of Y1 @ ec_Wproj^T, feat ) — fused epilogue
    gemm_epi<false, 2><<<BB * MM / 64, 256>>>(Y1, ec_Wproj, out_node, nullptr,
                                              ec_g, ec_b, vc_alpha, ec_alpha, feat);
}